// round 8
// baseline (speedup 1.0000x reference)
#include <cuda_runtime.h>
#include <math.h>

// Problem constants (shapes fixed by setup_inputs)
#define BB    16
#define CIMG  33
#define HIN   256
#define WIN   256
#define FH    128
#define FW    128
#define NF    10            // flow pairs
#define NPIX  (FH*FW)       // 16384
#define NCH   (NF*3)        // 30 compared channels
#define SPLIT 32            // pixel-range splits per (b,f)
#define WTHR  256           // threads in fused kernel
#define PPB   (NPIX/SPLIT)  // 512 pixels per block
#define ITERS (PPB/WTHR)    // 2
#define NSTAT 17            // s1[3],s2[3],s11[3],s22[3],s12[3],pix,smooth

// ---------------- scratch (static device memory only) -----------------------
__device__ float g_resized[BB*CIMG*NPIX];          // 34.6 MB
__device__ float g_stats[BB*NF*SPLIT*NSTAT];       // per-block partials

__device__ __forceinline__ float charb(float x) {
    // (x^2 + 1e-6)^0.4 via fast log2/exp2 (rel err ~2^-22, fine at 1e-3 gate)
    float v = fmaf(x, x, 1e-6f);
    return exp2f(0.4f * __log2f(v));
}

// ---------------- K1: align-corners bilinear resize 256^2 -> 128^2 ----------
// Output pair (2xh, 2xh+1) needs exactly input cols [4xh,4xh+4):
// one float4 per input row, 2 rows -> 2 perfectly-coalesced LDG.128/thread.
__global__ void resize_kernel(const float* __restrict__ img) {
    int t = blockIdx.x * blockDim.x + threadIdx.x;
    if (t >= BB * CIMG * FH * (FW / 2)) return;
    int xh = t & 63;            // output-pixel pair
    int y  = (t >> 6) & 127;
    int bc = t >> 13;

    const float sy = (float)((double)(HIN - 1) / (double)(FH - 1));
    const float sx = (float)((double)(WIN - 1) / (double)(FW - 1));

    float fy = (float)y * sy;
    int y0 = min(max((int)floorf(fy), 0), HIN - 2);
    float wy = fy - (float)y0;

    const float* p0 = img + (size_t)bc * (HIN * WIN) + y0 * WIN + xh * 4;
    float4 a = *(const float4*)(p0);
    float4 b = *(const float4*)(p0 + WIN);

    float va[4] = {a.x, a.y, a.z, a.w};
    float vb[4] = {b.x, b.y, b.z, b.w};

    float2 o;
    float* op = &o.x;
#pragma unroll
    for (int j = 0; j < 2; j++) {
        int x = xh * 2 + j;
        float fx = (float)x * sx;
        int x0 = min(max((int)floorf(fx), 0), WIN - 2);   // == 2x (clamped)
        float wx = fx - (float)x0;
        int c = x0 - xh * 4;                              // == 2j
        float rl = va[c]     * (1.f - wy) + vb[c]     * wy;
        float rr = va[c + 1] * (1.f - wy) + vb[c + 1] * wy;
        op[j] = rl * (1.f - wx) + rr * wx;
    }
    *(float2*)(g_resized + (size_t)bc * NPIX + y * FW + xh * 2) = o;
}

// ---------------- K2: fused warp + SSIM sums + pixel + smoothness -----------
// grid = BB*NF*SPLIT blocks, WTHR threads; block handles PPB pixels of (b,f).
__global__ void fused_loss_kernel(const float* __restrict__ flows) {
    __shared__ float sred[(WTHR/32)*NSTAT];
    int blk = blockIdx.x;
    int s  = blk & (SPLIT - 1);
    int bf = blk / SPLIT;
    int b  = bf / NF, f = bf % NF;
    int tid = threadIdx.x;

    const float* base = flows + (size_t)b * (2 * NF) * NPIX;
    const float* flx  = base + (size_t)(2 * f) * NPIX;
    const float* fly  = flx + NPIX;
    const float* ref0 = g_resized + (size_t)(b * CIMG + f * 3) * NPIX;
    const float* src0 = ref0 + 3 * NPIX;

    int pstart = s * PPB;

    // ---- phase 1: front-load all independent inputs (max MLP) ----
    float fxv[ITERS], fyv[ITERS];
    float nxp[ITERS], nxm[ITERS], nyp[ITERS], nym[ITERS]; // flow-index-axis nbrs
    float vxp[ITERS], vxm[ITERS], vyp[ITERS], vym[ITERS]; // H-axis nbrs
    float rv[ITERS][3];

#pragma unroll
    for (int it = 0; it < ITERS; it++) {
        int p = pstart + it * WTHR + tid;
        int y = p >> 7;
        fxv[it] = flx[p];
        fyv[it] = fly[p];
        if (f < NF - 1) { nxp[it] = __ldg(base + (2*f + 2) * NPIX + p);
                          nyp[it] = __ldg(base + (2*f + 3) * NPIX + p); }
        if (f > 0)      { nxm[it] = __ldg(base + (2*f - 2) * NPIX + p);
                          nym[it] = __ldg(base + (2*f - 1) * NPIX + p); }
        if (y < FH - 1) { vxp[it] = __ldg(flx + p + FW); vyp[it] = __ldg(fly + p + FW); }
        if (y > 0)      { vxm[it] = __ldg(flx + p - FW); vym[it] = __ldg(fly + p - FW); }
#pragma unroll
        for (int c = 0; c < 3; c++) rv[it][c] = __ldg(ref0 + c * NPIX + p);
    }

    // ---- phase 2: dependent gathers + math ----
    float s1[3]  = {0,0,0}, s2[3]  = {0,0,0};
    float s11[3] = {0,0,0}, s22[3] = {0,0,0}, s12[3] = {0,0,0};
    float pix = 0.f, smo = 0.f;

#pragma unroll
    for (int it = 0; it < ITERS; it++) {
        int p = pstart + it * WTHR + tid;
        int x = p & (FW - 1);
        int y = p >> 7;

        float gx = (float)x + fxv[it];
        float gy = (float)y + fyv[it];
        float x0f = floorf(gx), y0f = floorf(gy);
        float wx = gx - x0f, wy = gy - y0f;
        int x0 = min(max((int)x0f, 0), FW - 1);
        int x1 = min(x0 + 1, FW - 1);
        int y0 = min(max((int)y0f, 0), FH - 1);
        int y1 = min(y0 + 1, FH - 1);
        int i00 = y0 * FW + x0, i01 = y0 * FW + x1;
        int i10 = y1 * FW + x0, i11 = y1 * FW + x1;
#pragma unroll
        for (int c = 0; c < 3; c++) {
            const float* sc = src0 + c * NPIX;
            float r   = rv[it][c];
            float top = __ldg(sc + i00) * (1.f - wx) + __ldg(sc + i01) * wx;
            float bot = __ldg(sc + i10) * (1.f - wx) + __ldg(sc + i11) * wx;
            float wv  = top * (1.f - wy) + bot * wy;
            s1[c]  += r;
            s2[c]  += wv;
            s11[c] = fmaf(r, r, s11[c]);
            s22[c] = fmaf(wv, wv, s22[c]);
            s12[c] = fmaf(r, wv, s12[c]);
            pix    += charb(r - wv);
        }

        // smoothness (flow_x = ch 2f, flow_y = ch 2f+1)
        float g1x, g1y, g2x, g2y;
        if (f == 0)           { g1x = nxp[it] - fxv[it];          g1y = nyp[it] - fyv[it]; }
        else if (f == NF - 1) { g1x = fxv[it] - nxm[it];          g1y = fyv[it] - nym[it]; }
        else                  { g1x = (nxp[it] - nxm[it]) * 0.5f; g1y = (nyp[it] - nym[it]) * 0.5f; }
        if (y == 0)           { g2x = vxp[it] - fxv[it];          g2y = vyp[it] - fyv[it]; }
        else if (y == FH - 1) { g2x = fxv[it] - vxm[it];          g2y = fyv[it] - vym[it]; }
        else                  { g2x = (vxp[it] - vxm[it]) * 0.5f; g2y = (vyp[it] - vym[it]) * 0.5f; }
        smo += charb(g1x) + charb(g2x) + charb(g1y) + charb(g2y);
    }

    // ---- single combined reduction: 17 stats, one __syncthreads ----
    float st[NSTAT];
#pragma unroll
    for (int c = 0; c < 3; c++) {
        st[c]      = s1[c];
        st[3 + c]  = s2[c];
        st[6 + c]  = s11[c];
        st[9 + c]  = s22[c];
        st[12 + c] = s12[c];
    }
    st[15] = pix;
    st[16] = smo;

    int lane = tid & 31, w = tid >> 5;
#pragma unroll
    for (int k = 0; k < NSTAT; k++) {
        float v = st[k];
#pragma unroll
        for (int o = 16; o; o >>= 1) v += __shfl_down_sync(0xffffffffu, v, o);
        if (lane == 0) sred[w * NSTAT + k] = v;
    }
    __syncthreads();
    if (tid < NSTAT) {
        float v = 0.f;
#pragma unroll
        for (int w2 = 0; w2 < WTHR / 32; w2++) v += sred[w2 * NSTAT + tid];
        g_stats[blk * NSTAT + tid] = v;
    }
}

// ---------------- K3: finalize (all float) -----------------------------------
__global__ void finalize_kernel(float* __restrict__ out, int out_size) {
    __shared__ float fsh[512];
    int tid = threadIdx.x;
    const float N = (float)NPIX;

    float ssim_acc = 0.f;
    for (int ch = tid; ch < BB * NCH; ch += 512) {
        int bf = ch / 3, c = ch % 3;
        float S1 = 0, S2 = 0, S11 = 0, S22 = 0, S12 = 0;
#pragma unroll
        for (int sp = 0; sp < SPLIT; sp++) {
            const float* g = g_stats + (size_t)(bf * SPLIT + sp) * NSTAT;
            S1  += g[c];
            S2  += g[3 + c];
            S11 += g[6 + c];
            S22 += g[9 + c];
            S12 += g[12 + c];
        }
        float mu1 = S1 / N, mu2 = S2 / N;
        float var1 = (S11 - S1 * S1 / N) / (N - 1.f);
        float var2 = (S22 - S2 * S2 / N) / (N - 1.f);
        float cov  = (S12 - S1 * S2 / N) / N;
        float num = (2.f * mu1 * mu2 + 1e-4f) * (2.f * cov + 1e-3f);
        float den = (mu1 * mu1 + mu2 * mu2 + 1e-4f) * (var1 + var2 + 1e-3f);
        ssim_acc += num / den;
    }
    float pix_acc = 0.f, sm_acc = 0.f;
    for (int r = tid; r < BB * NF * SPLIT; r += 512) {
        pix_acc += g_stats[r * NSTAT + 15];
        sm_acc  += g_stats[r * NSTAT + 16];
    }

    fsh[tid] = ssim_acc; __syncthreads();
    for (int s = 256; s; s >>= 1) { if (tid < s) fsh[tid] += fsh[tid + s]; __syncthreads(); }
    float ssim_sum = fsh[0]; __syncthreads();

    fsh[tid] = pix_acc; __syncthreads();
    for (int s = 256; s; s >>= 1) { if (tid < s) fsh[tid] += fsh[tid + s]; __syncthreads(); }
    float pix_sum = fsh[0]; __syncthreads();

    fsh[tid] = sm_acc; __syncthreads();
    for (int s = 256; s; s >>= 1) { if (tid < s) fsh[tid] += fsh[tid + s]; __syncthreads(); }
    float sm_sum = fsh[0];

    if (tid == 0) {
        float ssim_mean = ssim_sum / (float)(BB * NCH);
        float pixel     = pix_sum  / (float)(BB * NCH * NPIX);
        float smooth    = sm_sum   / (float)(BB * NF * NPIX);
        float loss = pixel + 0.01f * smooth + ssim_mean;
        for (int k = 0; k < out_size; k++) out[k] = loss;
    }
}

// ---------------- launch ------------------------------------------------------
extern "C" void kernel_launch(void* const* d_in, const int* in_sizes, int n_in,
                              void* d_out, int out_size) {
    const float* images = (const float*)d_in[0];
    const float* flows  = (const float*)d_in[1];
    float* out = (float*)d_out;

    int rthreads = BB * CIMG * FH * (FW / 2);
    resize_kernel<<<(rthreads + 255) / 256, 256>>>(images);
    fused_loss_kernel<<<BB * NF * SPLIT, WTHR>>>(flows);
    finalize_kernel<<<1, 512>>>(out, out_size);
}

// round 9
// speedup vs baseline: 1.2792x; 1.2792x over previous
#include <cuda_runtime.h>
#include <math.h>

// Problem constants (shapes fixed by setup_inputs)
#define BB    16
#define CIMG  33
#define HIN   256
#define WIN   256
#define FH    128
#define FW    128
#define NF    10            // flow pairs
#define NPIX  (FH*FW)       // 16384
#define NCH   (NF*3)        // 30 compared channels
#define SPLIT 16            // pixel-range splits per (b,f)  (R7-best config)
#define WTHR  256           // threads in fused kernel
#define PPB   (NPIX/SPLIT)  // 1024 pixels per block
#define ITERS (PPB/WTHR)    // 4
#define NSTAT 17            // s1[3],s2[3],s11[3],s22[3],s12[3],pix,smooth

// ---------------- scratch (static device memory only) -----------------------
__device__ float g_resized[BB*CIMG*NPIX];          // 34.6 MB
__device__ float g_stats[BB*NF*SPLIT*NSTAT];       // per-block partials

__device__ __forceinline__ float charb(float x) {
    // (x^2 + 1e-6)^0.4 via fast log2/exp2 (rel err ~2^-22, fine at 1e-3 gate)
    float v = fmaf(x, x, 1e-6f);
    return exp2f(0.4f * __log2f(v));
}

// ---------------- K1: align-corners bilinear resize 256^2 -> 128^2 ----------
// scale = 255/127 = 2 + 1/127 exactly =>
//   x0 = 2x, wx = x/127 (exact incl. x=127: x0 clamps to 254, wx = 1)
// Output pair (2xh, 2xh+1) reads input cols [4xh,4xh+4) of two rows:
// 2 perfectly-coalesced LDG.128/thread, 1 STG.64. Zero floor/clamp ALU.
__global__ void resize_kernel(const float* __restrict__ img) {
    int t = blockIdx.x * blockDim.x + threadIdx.x;
    if (t >= BB * CIMG * FH * (FW / 2)) return;
    int xh = t & 63;            // output-pixel pair index
    int y  = (t >> 6) & 127;
    int bc = t >> 13;

    const float inv127 = 1.f / 127.f;
    float wy = (float)y * inv127;

    const float* p0 = img + (size_t)bc * (HIN * WIN) + (2 * y) * WIN + xh * 4;
    float4 a = *(const float4*)(p0);
    float4 b = *(const float4*)(p0 + WIN);

    float wx0 = (float)(xh * 2)     * inv127;
    float wx1 = (float)(xh * 2 + 1) * inv127;

    // y-interp first, then x-interp (reference association order)
    float m0 = a.x * (1.f - wy) + b.x * wy;
    float m1 = a.y * (1.f - wy) + b.y * wy;
    float m2 = a.z * (1.f - wy) + b.z * wy;
    float m3 = a.w * (1.f - wy) + b.w * wy;

    float2 o;
    o.x = m0 * (1.f - wx0) + m1 * wx0;
    o.y = m2 * (1.f - wx1) + m3 * wx1;
    *(float2*)(g_resized + (size_t)bc * NPIX + y * FW + xh * 2) = o;
}

// ---------------- K2: fused warp + SSIM sums + pixel + smoothness -----------
// grid = BB*NF*SPLIT blocks, WTHR threads; block handles PPB pixels of (b,f).
__global__ void fused_loss_kernel(const float* __restrict__ flows) {
    __shared__ float sred[(WTHR/32)*NSTAT];
    int blk = blockIdx.x;
    int s  = blk & (SPLIT - 1);
    int bf = blk / SPLIT;
    int b  = bf / NF, f = bf % NF;
    int tid = threadIdx.x;

    const float* base = flows + (size_t)b * (2 * NF) * NPIX;
    const float* flx  = base + (size_t)(2 * f) * NPIX;
    const float* fly  = flx + NPIX;
    const float* ref0 = g_resized + (size_t)(b * CIMG + f * 3) * NPIX;
    const float* src0 = ref0 + 3 * NPIX;

    int pstart = s * PPB;

    // ---- phase 1: front-load all independent inputs (max MLP) ----
    float fxv[ITERS], fyv[ITERS];
    float nxp[ITERS], nxm[ITERS], nyp[ITERS], nym[ITERS]; // flow-index-axis nbrs
    float vxp[ITERS], vxm[ITERS], vyp[ITERS], vym[ITERS]; // H-axis nbrs
    float rv[ITERS][3];

#pragma unroll
    for (int it = 0; it < ITERS; it++) {
        int p = pstart + it * WTHR + tid;
        int y = p >> 7;
        fxv[it] = flx[p];
        fyv[it] = fly[p];
        if (f < NF - 1) { nxp[it] = __ldg(base + (2*f + 2) * NPIX + p);
                          nyp[it] = __ldg(base + (2*f + 3) * NPIX + p); }
        if (f > 0)      { nxm[it] = __ldg(base + (2*f - 2) * NPIX + p);
                          nym[it] = __ldg(base + (2*f - 1) * NPIX + p); }
        if (y < FH - 1) { vxp[it] = __ldg(flx + p + FW); vyp[it] = __ldg(fly + p + FW); }
        if (y > 0)      { vxm[it] = __ldg(flx + p - FW); vym[it] = __ldg(fly + p - FW); }
#pragma unroll
        for (int c = 0; c < 3; c++) rv[it][c] = __ldg(ref0 + c * NPIX + p);
    }

    // ---- phase 2: dependent gathers + math ----
    float s1[3]  = {0,0,0}, s2[3]  = {0,0,0};
    float s11[3] = {0,0,0}, s22[3] = {0,0,0}, s12[3] = {0,0,0};
    float pix = 0.f, smo = 0.f;

#pragma unroll
    for (int it = 0; it < ITERS; it++) {
        int p = pstart + it * WTHR + tid;
        int x = p & (FW - 1);
        int y = p >> 7;

        float gx = (float)x + fxv[it];
        float gy = (float)y + fyv[it];
        float x0f = floorf(gx), y0f = floorf(gy);
        float wx = gx - x0f, wy = gy - y0f;
        int x0 = min(max((int)x0f, 0), FW - 1);
        int x1 = min(x0 + 1, FW - 1);
        int y0 = min(max((int)y0f, 0), FH - 1);
        int y1 = min(y0 + 1, FH - 1);
        int i00 = y0 * FW + x0, i01 = y0 * FW + x1;
        int i10 = y1 * FW + x0, i11 = y1 * FW + x1;
#pragma unroll
        for (int c = 0; c < 3; c++) {
            const float* sc = src0 + c * NPIX;
            float r   = rv[it][c];
            float top = __ldg(sc + i00) * (1.f - wx) + __ldg(sc + i01) * wx;
            float bot = __ldg(sc + i10) * (1.f - wx) + __ldg(sc + i11) * wx;
            float wv  = top * (1.f - wy) + bot * wy;
            s1[c]  += r;
            s2[c]  += wv;
            s11[c] = fmaf(r, r, s11[c]);
            s22[c] = fmaf(wv, wv, s22[c]);
            s12[c] = fmaf(r, wv, s12[c]);
            pix    += charb(r - wv);
        }

        // smoothness (flow_x = ch 2f, flow_y = ch 2f+1)
        float g1x, g1y, g2x, g2y;
        if (f == 0)           { g1x = nxp[it] - fxv[it];          g1y = nyp[it] - fyv[it]; }
        else if (f == NF - 1) { g1x = fxv[it] - nxm[it];          g1y = fyv[it] - nym[it]; }
        else                  { g1x = (nxp[it] - nxm[it]) * 0.5f; g1y = (nyp[it] - nym[it]) * 0.5f; }
        if (y == 0)           { g2x = vxp[it] - fxv[it];          g2y = vyp[it] - fyv[it]; }
        else if (y == FH - 1) { g2x = fxv[it] - vxm[it];          g2y = fyv[it] - vym[it]; }
        else                  { g2x = (vxp[it] - vxm[it]) * 0.5f; g2y = (vyp[it] - vym[it]) * 0.5f; }
        smo += charb(g1x) + charb(g2x) + charb(g1y) + charb(g2y);
    }

    // ---- single combined reduction: 17 stats, one __syncthreads ----
    float st[NSTAT];
#pragma unroll
    for (int c = 0; c < 3; c++) {
        st[c]      = s1[c];
        st[3 + c]  = s2[c];
        st[6 + c]  = s11[c];
        st[9 + c]  = s22[c];
        st[12 + c] = s12[c];
    }
    st[15] = pix;
    st[16] = smo;

    int lane = tid & 31, w = tid >> 5;
#pragma unroll
    for (int k = 0; k < NSTAT; k++) {
        float v = st[k];
#pragma unroll
        for (int o = 16; o; o >>= 1) v += __shfl_down_sync(0xffffffffu, v, o);
        if (lane == 0) sred[w * NSTAT + k] = v;
    }
    __syncthreads();
    if (tid < NSTAT) {
        float v = 0.f;
#pragma unroll
        for (int w2 = 0; w2 < WTHR / 32; w2++) v += sred[w2 * NSTAT + tid];
        g_stats[blk * NSTAT + tid] = v;
    }
}

// ---------------- K3: finalize (all float) -----------------------------------
__global__ void finalize_kernel(float* __restrict__ out, int out_size) {
    __shared__ float fsh[512];
    int tid = threadIdx.x;
    const float N = (float)NPIX;

    float ssim_acc = 0.f;
    for (int ch = tid; ch < BB * NCH; ch += 512) {
        int bf = ch / 3, c = ch % 3;
        float S1 = 0, S2 = 0, S11 = 0, S22 = 0, S12 = 0;
#pragma unroll
        for (int sp = 0; sp < SPLIT; sp++) {
            const float* g = g_stats + (size_t)(bf * SPLIT + sp) * NSTAT;
            S1  += g[c];
            S2  += g[3 + c];
            S11 += g[6 + c];
            S22 += g[9 + c];
            S12 += g[12 + c];
        }
        float mu1 = S1 / N, mu2 = S2 / N;
        float var1 = (S11 - S1 * S1 / N) / (N - 1.f);
        float var2 = (S22 - S2 * S2 / N) / (N - 1.f);
        float cov  = (S12 - S1 * S2 / N) / N;
        float num = (2.f * mu1 * mu2 + 1e-4f) * (2.f * cov + 1e-3f);
        float den = (mu1 * mu1 + mu2 * mu2 + 1e-4f) * (var1 + var2 + 1e-3f);
        ssim_acc += num / den;
    }
    float pix_acc = 0.f, sm_acc = 0.f;
    for (int r = tid; r < BB * NF * SPLIT; r += 512) {
        pix_acc += g_stats[r * NSTAT + 15];
        sm_acc  += g_stats[r * NSTAT + 16];
    }

    fsh[tid] = ssim_acc; __syncthreads();
    for (int s = 256; s; s >>= 1) { if (tid < s) fsh[tid] += fsh[tid + s]; __syncthreads(); }
    float ssim_sum = fsh[0]; __syncthreads();

    fsh[tid] = pix_acc; __syncthreads();
    for (int s = 256; s; s >>= 1) { if (tid < s) fsh[tid] += fsh[tid + s]; __syncthreads(); }
    float pix_sum = fsh[0]; __syncthreads();

    fsh[tid] = sm_acc; __syncthreads();
    for (int s = 256; s; s >>= 1) { if (tid < s) fsh[tid] += fsh[tid + s]; __syncthreads(); }
    float sm_sum = fsh[0];

    if (tid == 0) {
        float ssim_mean = ssim_sum / (float)(BB * NCH);
        float pixel     = pix_sum  / (float)(BB * NCH * NPIX);
        float smooth    = sm_sum   / (float)(BB * NF * NPIX);
        float loss = pixel + 0.01f * smooth + ssim_mean;
        for (int k = 0; k < out_size; k++) out[k] = loss;
    }
}

// ---------------- launch ------------------------------------------------------
extern "C" void kernel_launch(void* const* d_in, const int* in_sizes, int n_in,
                              void* d_out, int out_size) {
    const float* images = (const float*)d_in[0];
    const float* flows  = (const float*)d_in[1];
    float* out = (float*)d_out;

    int rthreads = BB * CIMG * FH * (FW / 2);
    resize_kernel<<<(rthreads + 255) / 256, 256>>>(images);
    fused_loss_kernel<<<BB * NF * SPLIT, WTHR>>>(flows);
    finalize_kernel<<<1, 512>>>(out, out_size);
}